// round 13
// baseline (speedup 1.0000x reference)
#include <cuda_runtime.h>
#include <cuda_bf16.h>

// VGAE encoder, pull-based, rank-1 norm factored out:
//   norm_ij = dis_i*dis_j  =>  out_i = dis_i * (u_i + sum_{j in N(i)} u_j),  u = dis (.) h.
// Each layer stores its output pre-scaled by dis (relu commutes with dis>0), so the
// CSR payload is src-only (int), and the gather loop has no per-edge weights.
// Layer = warp-per-node gather (float2 lane-split, int4 adj loads) + smem GEMV
// (t staged per-warp, W transposed in smem, float4 loads; no shuffles).

#define N_MAX 131072
#define E_MAX 2097152   // >= E + 3*N (per-node padding to 4)

// Scratch (device globals; no allocations allowed)
__device__ int   g_is64;
__device__ int   g_alloc;            // CSR region allocator
__device__ int   g_cnt[N_MAX];       // in-degree (excluding self-loop)
__device__ int   g_rowstart[N_MAX];
__device__ int   g_cur[N_MAX];       // permutation cursor
__device__ float g_dis[N_MAX];       // deg^-1/2 (deg includes self-loop)
__device__ int   g_adjs[E_MAX];      // CSR payload: src only
__device__ float g_bufA[(size_t)N_MAX * 32];
__device__ float g_bufB[(size_t)N_MAX * 32];

// ---------------------------------------------------------------------------
// Init: zero g_cnt (all blocks); block 0 also detects edge dtype.
// ---------------------------------------------------------------------------

__global__ __launch_bounds__(256) void k_init(const int* __restrict__ ei32,
                                              int E, int n) {
    int i = blockIdx.x * blockDim.x + threadIdx.x;
    if (i < n) g_cnt[i] = 0;
    if (blockIdx.x == 0) {
        int t = threadIdx.x;
        int n_check = 256 < E ? 256 : E;
        int nz = (t < n_check && ei32[2 * t + 1] != 0) ? 1 : 0;
        int any = __syncthreads_or(nz);
        if (t == 0) {
            g_is64 = !any;
            g_alloc = 0;
        }
    }
}

// Count in-degrees, 4 edges per thread (vectorized loads).
__global__ __launch_bounds__(256) void k_count(const void* __restrict__ eiv, int E) {
    int t = blockIdx.x * blockDim.x + threadIdx.x;
    int e0 = t * 4;
    if (e0 >= E) return;
    int d[4];
    int m = (E - e0 < 4) ? (E - e0) : 4;
    if (g_is64) {
        const long long* ei = (const long long*)eiv + (size_t)E + e0;
        if (m == 4) {
            longlong2 a = ((const longlong2*)ei)[0];
            longlong2 b = ((const longlong2*)ei)[1];
            d[0] = (int)a.x; d[1] = (int)a.y; d[2] = (int)b.x; d[3] = (int)b.y;
        } else {
            for (int k = 0; k < m; k++) d[k] = (int)ei[k];
        }
    } else {
        const int* ei = (const int*)eiv + (size_t)E + e0;
        if (m == 4) {
            int4 a = *(const int4*)ei;
            d[0] = a.x; d[1] = a.y; d[2] = a.z; d[3] = a.w;
        } else {
            for (int k = 0; k < m; k++) d[k] = ei[k];
        }
    }
    for (int k = 0; k < m; k++) atomicAdd(&g_cnt[d[k]], 1);
}

// Warp-per-node: CSR region alloc (lane 0) fused with u1 = dis (.) x (all lanes).
__global__ __launch_bounds__(256) void k_rowalloc(const float* __restrict__ x,
                                                  float* __restrict__ u, int n) {
    int warp = (blockIdx.x * blockDim.x + threadIdx.x) >> 5;
    int lane = threadIdx.x & 31;
    if (warp >= n) return;
    int c = 0;
    if (lane == 0) {
        c = g_cnt[warp];
        int rs = atomicAdd(&g_alloc, (c + 3) & ~3);
        g_rowstart[warp] = rs;
        g_cur[warp] = rs;
    }
    c = __shfl_sync(0xFFFFFFFFu, c, 0);
    float dis = rsqrtf((float)(c + 1));  // +1 self-loop
    if (lane == 0) g_dis[warp] = dis;
    int idx = warp * 32 + lane;
    u[idx] = dis * x[idx];
}

// Permute edges into CSR (1 edge per thread).
__global__ void k_permute(const void* __restrict__ eiv, int E) {
    int e = blockIdx.x * blockDim.x + threadIdx.x;
    if (e >= E) return;
    int s, d;
    if (g_is64) {
        const long long* ei = (const long long*)eiv;
        s = (int)ei[e];
        d = (int)ei[(size_t)E + e];
    } else {
        const int* ei = (const int*)eiv;
        s = ei[e];
        d = ei[(size_t)E + e];
    }
    int pos = atomicAdd(&g_cur[d], 1);
    g_adjs[pos] = s;
}

// ---------------------------------------------------------------------------
// Fused layer: warp = node; half-warps take alternating 4-edge int4 chunks;
// lane holds channels (2*sub, 2*sub+1) as float2.
//   t = r(u_i) + sum_j r(u_src_j);  o = b + dis*(t @ W);  out = PRE ? dis*o : o
// GEMV: t staged to per-warp smem, W transposed in smem (pitch 36), float4 loads.
// ---------------------------------------------------------------------------

__device__ __forceinline__ float2 relu2(float2 v) {
    v.x = fmaxf(v.x, 0.0f); v.y = fmaxf(v.y, 0.0f); return v;
}

template <int RELU, int PRE_OUT>
__global__ __launch_bounds__(256) void k_layer(
    const float* __restrict__ u, const float* __restrict__ W,
    const float* __restrict__ b, float* __restrict__ out, int n)
{
    __shared__ float4 sWtv[288];   // W transposed: sWt[j*36 + k] = W[k][j]
    __shared__ float4 sTv[64];     // 8 warps x 32 floats (t rows)
    float* sWt = (float*)sWtv;
    float* sT  = (float*)sTv;
    int tid = threadIdx.x;
#pragma unroll
    for (int it = 0; it < 4; it++) {
        int idx = tid + it * 256;
        float w = W[idx];
        int k = idx >> 5, j = idx & 31;
        sWt[j * 36 + k] = w;
    }
    __syncthreads();

    int warp = (blockIdx.x * blockDim.x + tid) >> 5;
    int lane = tid & 31;
    if (warp >= n) return;

    int half = lane >> 4;      // 0 or 1
    int sub  = lane & 15;      // channel pair index
    const float2* u2 = (const float2*)u;

    int rs  = g_rowstart[warp];
    int cnt = g_cnt[warp];
    float dis = g_dis[warp];
    float bv = b[lane];        // hoisted: off the epilogue's dependent chain

    // self term (half 0 only; halves summed later)
    float2 acc = make_float2(0.0f, 0.0f);
    if (half == 0) {
        float2 sv = u2[warp * 16 + sub];
        if (RELU) sv = relu2(sv);
        acc = sv;
    }

    int j = rs, end = rs + cnt;
    // 8 edges per iteration: each half-warp loads one int4 (4 src indices)
    for (; j + 8 <= end; j += 8) {
        int4 e = *(const int4*)(g_adjs + j + 4 * half);
        float2 v0 = u2[e.x * 16 + sub];
        float2 v1 = u2[e.y * 16 + sub];
        float2 v2 = u2[e.z * 16 + sub];
        float2 v3 = u2[e.w * 16 + sub];
        if (RELU) { v0 = relu2(v0); v1 = relu2(v1); v2 = relu2(v2); v3 = relu2(v3); }
        acc.x += (v0.x + v1.x) + (v2.x + v3.x);
        acc.y += (v0.y + v1.y) + (v2.y + v3.y);
    }
    for (; j + 2 <= end; j += 2) {
        float2 v = u2[g_adjs[j + half] * 16 + sub];
        if (RELU) v = relu2(v);
        acc.x += v.x; acc.y += v.y;
    }
    if (j < end && half == 0) {
        float2 v = u2[g_adjs[j] * 16 + sub];
        if (RELU) v = relu2(v);
        acc.x += v.x; acc.y += v.y;
    }

    // combine halves, half 0 stages the t row into per-warp smem
    acc.x += __shfl_xor_sync(0xFFFFFFFFu, acc.x, 16);
    acc.y += __shfl_xor_sync(0xFFFFFFFFu, acc.y, 16);
    int wslot = (tid >> 5) * 32;
    if (half == 0) *(float2*)(sT + wslot + 2 * sub) = acc;
    __syncwarp();

    // GEMV: s = sum_k t[k] * W[k][lane]  (broadcast t, per-lane W row)
    float s = 0.0f;
    const float4* t4p = (const float4*)(sT + wslot);
    const float* wr = sWt + lane * 36;
#pragma unroll
    for (int q = 0; q < 8; q++) {
        float4 t4 = t4p[q];
        float4 w4 = *(const float4*)(wr + 4 * q);
        s += t4.x * w4.x + t4.y * w4.y;
        s += t4.z * w4.z + t4.w * w4.w;
    }
    float sb = PRE_OUT ? dis : 1.0f;
    float ss = PRE_OUT ? dis * dis : dis;
    out[warp * 32 + lane] = sb * bv + ss * s;
}

// Fused dual head: one aggregation, two smem GEMVs (mu and logvar).
__global__ __launch_bounds__(256) void k_layer2(
    const float* __restrict__ u,
    const float* __restrict__ Wa, const float* __restrict__ Wb,
    const float* __restrict__ ba, const float* __restrict__ bb,
    float* __restrict__ oa, float* __restrict__ ob, int n)
{
    __shared__ float4 sWtav[288];
    __shared__ float4 sWtbv[288];
    __shared__ float4 sTv[64];
    float* sWta = (float*)sWtav;
    float* sWtb = (float*)sWtbv;
    float* sT   = (float*)sTv;
    int tid = threadIdx.x;
#pragma unroll
    for (int it = 0; it < 4; it++) {
        int idx = tid + it * 256;
        float wa = Wa[idx];
        float wb = Wb[idx];
        int k = idx >> 5, j = idx & 31;
        sWta[j * 36 + k] = wa;
        sWtb[j * 36 + k] = wb;
    }
    __syncthreads();

    int warp = (blockIdx.x * blockDim.x + tid) >> 5;
    int lane = tid & 31;
    if (warp >= n) return;

    int half = lane >> 4;
    int sub  = lane & 15;
    const float2* u2 = (const float2*)u;

    int rs  = g_rowstart[warp];
    int cnt = g_cnt[warp];
    float dis = g_dis[warp];
    float bav = ba[lane];   // hoisted
    float bbv = bb[lane];   // hoisted

    float2 acc = make_float2(0.0f, 0.0f);
    if (half == 0) acc = relu2(u2[warp * 16 + sub]);

    int j = rs, end = rs + cnt;
    for (; j + 8 <= end; j += 8) {
        int4 e = *(const int4*)(g_adjs + j + 4 * half);
        float2 v0 = relu2(u2[e.x * 16 + sub]);
        float2 v1 = relu2(u2[e.y * 16 + sub]);
        float2 v2 = relu2(u2[e.z * 16 + sub]);
        float2 v3 = relu2(u2[e.w * 16 + sub]);
        acc.x += (v0.x + v1.x) + (v2.x + v3.x);
        acc.y += (v0.y + v1.y) + (v2.y + v3.y);
    }
    for (; j + 2 <= end; j += 2) {
        float2 v = relu2(u2[g_adjs[j + half] * 16 + sub]);
        acc.x += v.x; acc.y += v.y;
    }
    if (j < end && half == 0) {
        float2 v = relu2(u2[g_adjs[j] * 16 + sub]);
        acc.x += v.x; acc.y += v.y;
    }

    acc.x += __shfl_xor_sync(0xFFFFFFFFu, acc.x, 16);
    acc.y += __shfl_xor_sync(0xFFFFFFFFu, acc.y, 16);
    int wslot = (tid >> 5) * 32;
    if (half == 0) *(float2*)(sT + wslot + 2 * sub) = acc;
    __syncwarp();

    float sa = 0.0f, sb = 0.0f;
    const float4* t4p = (const float4*)(sT + wslot);
    const float* wra = sWta + lane * 36;
    const float* wrb = sWtb + lane * 36;
#pragma unroll
    for (int q = 0; q < 8; q++) {
        float4 t4 = t4p[q];
        float4 wa = *(const float4*)(wra + 4 * q);
        float4 wb = *(const float4*)(wrb + 4 * q);
        sa += t4.x * wa.x + t4.y * wa.y;
        sa += t4.z * wa.z + t4.w * wa.w;
        sb += t4.x * wb.x + t4.y * wb.y;
        sb += t4.z * wb.z + t4.w * wb.w;
    }
    int self = warp * 32 + lane;
    oa[self] = bav + dis * sa;
    ob[self] = bbv + dis * sb;
}

// ---------------------------------------------------------------------------
// Launch
// ---------------------------------------------------------------------------

static inline int cdiv(long long a, int b) { return (int)((a + b - 1) / b); }

extern "C" void kernel_launch(void* const* d_in, const int* in_sizes, int n_in,
                              void* d_out, int out_size)
{
    const float* x   = (const float*)d_in[0];
    const void*  ei  = d_in[1];
    const float* W1  = (const float*)d_in[2];
    const float* b1  = (const float*)d_in[3];
    const float* W2  = (const float*)d_in[4];
    const float* b2  = (const float*)d_in[5];
    const float* Wmu = (const float*)d_in[6];
    const float* bmu = (const float*)d_in[7];
    const float* Wlv = (const float*)d_in[8];
    const float* blv = (const float*)d_in[9];

    int N = in_sizes[0] / 32;
    int E = in_sizes[1] / 2;

    float* mu = (float*)d_out;
    float* lv = mu + (size_t)N * 32;

    float* bufA; float* bufB;
    cudaGetSymbolAddress((void**)&bufA, g_bufA);
    cudaGetSymbolAddress((void**)&bufB, g_bufB);

    const int T = 256;
    int gN  = cdiv(N, T);                  // per-node
    int gE  = cdiv(E, T);                  // per-edge
    int gE4 = cdiv(E, T * 4);              // 4 edges per thread
    int gW  = cdiv((long long)N * 32, T);  // warp-per-node

    // CSR build (src-only payload); rowalloc fused with layer-1 pre-scale
    k_init<<<gN, T>>>((const int*)ei, E, N);
    k_count<<<gE4, T>>>(ei, E);
    k_rowalloc<<<gW, T>>>(x, bufA, N);     // alloc + u1 = dis (.) x
    k_permute<<<gE, T>>>(ei, E);

    // Layer 1: u2 = dis (.) ((A u1) @ W1 + b1)
    k_layer<0, 1><<<gW, T>>>(bufA, W1, b1, bufB, N);
    // Layer 2: u3 = dis (.) ((A r(u2)) @ W2 + b2)
    k_layer<1, 1><<<gW, T>>>(bufB, W2, b2, bufA, N);
    // Heads: t = A r(u3); mu = dis*(t@Wmu) + bmu; lv = dis*(t@Wlv) + blv
    k_layer2<<<gW, T>>>(bufA, Wmu, Wlv, bmu, blv, mu, lv, N);
}

// round 14
// speedup vs baseline: 1.4805x; 1.4805x over previous
#include <cuda_runtime.h>
#include <cuda_bf16.h>

// VGAE encoder, pull-based, rank-1 norm factored out:
//   norm_ij = dis_i*dis_j  =>  out_i = dis_i * (u_i + sum_{j in N(i)} u_j),  u = dis (.) h.
// Activations stored pre-scaled by dis (relu commutes, dis>0); CSR payload src-only.
// Rows padded to x4 with self-index (compensated in acc init) -> divergence-free
// int4 gather loops. Layers: HALF-WARP per node (2 nodes per warp, concurrent
// gathers) + smem GEMV epilogue (transposed W, float4 loads), run per node.
// CRITICAL: g_alloc atomic stays thread-per-node (32 same-address atomics/warp)
// so ptxas warp-aggregates it; single-lane form costs ~60us serialized atomics.

#define N_MAX 131072
#define E_MAX 2097152   // >= E + 3*N (per-node padding to 4)

// Scratch (device globals; no allocations allowed)
__device__ int   g_is64;
__device__ int   g_alloc;            // CSR region allocator
__device__ int   g_cnt[N_MAX];       // in-degree (excluding self-loop)
__device__ int   g_rowstart[N_MAX];
__device__ int   g_cur[N_MAX];       // permutation cursor
__device__ float g_dis[N_MAX];       // deg^-1/2 (deg includes self-loop)
__device__ int   g_adjs[E_MAX];      // CSR payload: src only (padded with self)
__device__ float g_bufA[(size_t)N_MAX * 32];
__device__ float g_bufB[(size_t)N_MAX * 32];

// ---------------------------------------------------------------------------
// Init: zero g_cnt (all blocks); block 0 also detects edge dtype.
// ---------------------------------------------------------------------------

__global__ __launch_bounds__(256) void k_init(const int* __restrict__ ei32,
                                              int E, int n) {
    int i = blockIdx.x * blockDim.x + threadIdx.x;
    if (i < n) g_cnt[i] = 0;
    if (blockIdx.x == 0) {
        int t = threadIdx.x;
        int n_check = 256 < E ? 256 : E;
        int nz = (t < n_check && ei32[2 * t + 1] != 0) ? 1 : 0;
        int any = __syncthreads_or(nz);
        if (t == 0) {
            g_is64 = !any;
            g_alloc = 0;
        }
    }
}

// Count in-degrees, 4 edges per thread (vectorized loads).
__global__ __launch_bounds__(256) void k_count(const void* __restrict__ eiv, int E) {
    int t = blockIdx.x * blockDim.x + threadIdx.x;
    int e0 = t * 4;
    if (e0 >= E) return;
    int d[4];
    int m = (E - e0 < 4) ? (E - e0) : 4;
    if (g_is64) {
        const long long* ei = (const long long*)eiv + (size_t)E + e0;
        if (m == 4) {
            longlong2 a = ((const longlong2*)ei)[0];
            longlong2 b = ((const longlong2*)ei)[1];
            d[0] = (int)a.x; d[1] = (int)a.y; d[2] = (int)b.x; d[3] = (int)b.y;
        } else {
            for (int k = 0; k < m; k++) d[k] = (int)ei[k];
        }
    } else {
        const int* ei = (const int*)eiv + (size_t)E + e0;
        if (m == 4) {
            int4 a = *(const int4*)ei;
            d[0] = a.x; d[1] = a.y; d[2] = a.z; d[3] = a.w;
        } else {
            for (int k = 0; k < m; k++) d[k] = ei[k];
        }
    }
    for (int k = 0; k < m; k++) atomicAdd(&g_cnt[d[k]], 1);
}

// Atomic CSR region allocation (thread-per-node => ptxas warp-aggregates the
// same-address atomic). Pads rows to x4 with the node's own index.
__global__ void k_rowalloc(int n) {
    int i = blockIdx.x * blockDim.x + threadIdx.x;
    if (i >= n) return;
    int c = g_cnt[i];
    int pc = (c + 3) & ~3;
    int rs = atomicAdd(&g_alloc, pc);
    g_rowstart[i] = rs;
    g_cur[i] = rs;
    g_dis[i] = rsqrtf((float)(c + 1));  // +1 self-loop
    for (int k = c; k < pc; k++) g_adjs[rs + k] = i;  // self-index padding
}

// u = dis (.) x  (layer-1 input pre-scale)
__global__ __launch_bounds__(256) void k_prescale(const float* __restrict__ x,
                                                  float* __restrict__ u, int n) {
    int i = blockIdx.x * blockDim.x + threadIdx.x;
    if (i >= n * 16) return;
    float s = g_dis[i >> 4];
    float2 v = ((const float2*)x)[i];
    v.x *= s; v.y *= s;
    ((float2*)u)[i] = v;
}

// Permute edges into CSR (1 edge per thread).
__global__ void k_permute(const void* __restrict__ eiv, int E) {
    int e = blockIdx.x * blockDim.x + threadIdx.x;
    if (e >= E) return;
    int s, d;
    if (g_is64) {
        const long long* ei = (const long long*)eiv;
        s = (int)ei[e];
        d = (int)ei[(size_t)E + e];
    } else {
        const int* ei = (const int*)eiv;
        s = ei[e];
        d = ei[(size_t)E + e];
    }
    int pos = atomicAdd(&g_cur[d], 1);
    g_adjs[pos] = s;
}

// ---------------------------------------------------------------------------
// Fused layer: HALF-WARP per node (node = warp*2 + half); lane holds channels
// (2*sub, 2*sub+1) as float2. Rows padded to x4 with self (compensated), so the
// gather is a clean int4 loop per half-warp; both nodes gather concurrently.
//   t = (1-pad)*r(u_i) + sum over padded row of r(u_src)
//   o = b + dis*(t @ W);  out = PRE_OUT ? dis*o : o
// Epilogue: t rows staged to smem; full warp runs one GEMV per node
// (broadcast t float4s, per-lane transposed-W row, conflict-free pitch 36).
// ---------------------------------------------------------------------------

__device__ __forceinline__ float2 relu2(float2 v) {
    v.x = fmaxf(v.x, 0.0f); v.y = fmaxf(v.y, 0.0f); return v;
}

template <int RELU, int PRE_OUT>
__global__ __launch_bounds__(256) void k_layer(
    const float* __restrict__ u, const float* __restrict__ W,
    const float* __restrict__ b, float* __restrict__ out, int n)
{
    __shared__ float4 sWtv[288];   // W transposed: sWt[j*36 + k] = W[k][j]
    __shared__ float4 sTv[128];    // 8 warps x 2 nodes x 32 floats
    float* sWt = (float*)sWtv;
    float* sT  = (float*)sTv;
    int tid = threadIdx.x;
#pragma unroll
    for (int it = 0; it < 4; it++) {
        int idx = tid + it * 256;
        float w = W[idx];
        int k = idx >> 5, j = idx & 31;
        sWt[j * 36 + k] = w;
    }
    __syncthreads();

    int warp = (blockIdx.x * blockDim.x + tid) >> 5;
    int lane = tid & 31;
    int half = lane >> 4;      // 0 or 1
    int sub  = lane & 15;      // channel pair index
    int node = warp * 2 + half;
    bool alive = node < n;

    const float2* u2 = (const float2*)u;
    float bv = b[lane];        // hoisted off the epilogue's dependent chain

    int cnt = 0;
    float2 acc = make_float2(0.0f, 0.0f);
    if (alive) {
        int rs = g_rowstart[node];
        cnt = g_cnt[node];
        int pc = (cnt + 3) & ~3;
        float2 sv = u2[node * 16 + sub];
        if (RELU) sv = relu2(sv);
        float comp = (float)(1 - (pc - cnt));
        acc.x = comp * sv.x;
        acc.y = comp * sv.y;
        for (int j = rs; j < rs + pc; j += 4) {
            int4 e = *(const int4*)(g_adjs + j);
            float2 v0 = u2[e.x * 16 + sub];
            float2 v1 = u2[e.y * 16 + sub];
            float2 v2 = u2[e.z * 16 + sub];
            float2 v3 = u2[e.w * 16 + sub];
            if (RELU) { v0 = relu2(v0); v1 = relu2(v1); v2 = relu2(v2); v3 = relu2(v3); }
            acc.x += (v0.x + v1.x) + (v2.x + v3.x);
            acc.y += (v0.y + v1.y) + (v2.y + v3.y);
        }
    }

    // stage both nodes' t rows
    int wslot = (tid >> 5) * 64;
    *(float2*)(sT + wslot + half * 32 + 2 * sub) = acc;
    __syncwarp();

    // two full-warp GEMVs, one per node
    int warp2 = warp * 2;
#pragma unroll
    for (int h = 0; h < 2; h++) {
        int nd = warp2 + h;
        if (nd >= n) break;
        int cn = __shfl_sync(0xFFFFFFFFu, cnt, h << 4);
        float dis = rsqrtf((float)(cn + 1));
        const float4* t4p = (const float4*)(sT + wslot + h * 32);
        const float* wr = sWt + lane * 36;
        float s = 0.0f;
#pragma unroll
        for (int q = 0; q < 8; q++) {
            float4 t4 = t4p[q];
            float4 w4 = *(const float4*)(wr + 4 * q);
            s += t4.x * w4.x + t4.y * w4.y;
            s += t4.z * w4.z + t4.w * w4.w;
        }
        float sb = PRE_OUT ? dis : 1.0f;
        float ss = PRE_OUT ? dis * dis : dis;
        out[nd * 32 + lane] = sb * bv + ss * s;
    }
}

// Fused dual head: one aggregation per node, two smem GEMVs (mu and logvar).
__global__ __launch_bounds__(256) void k_layer2(
    const float* __restrict__ u,
    const float* __restrict__ Wa, const float* __restrict__ Wb,
    const float* __restrict__ ba, const float* __restrict__ bb,
    float* __restrict__ oa, float* __restrict__ ob, int n)
{
    __shared__ float4 sWtav[288];
    __shared__ float4 sWtbv[288];
    __shared__ float4 sTv[128];
    float* sWta = (float*)sWtav;
    float* sWtb = (float*)sWtbv;
    float* sT   = (float*)sTv;
    int tid = threadIdx.x;
#pragma unroll
    for (int it = 0; it < 4; it++) {
        int idx = tid + it * 256;
        float wa = Wa[idx];
        float wb = Wb[idx];
        int k = idx >> 5, j = idx & 31;
        sWta[j * 36 + k] = wa;
        sWtb[j * 36 + k] = wb;
    }
    __syncthreads();

    int warp = (blockIdx.x * blockDim.x + tid) >> 5;
    int lane = tid & 31;
    int half = lane >> 4;
    int sub  = lane & 15;
    int node = warp * 2 + half;
    bool alive = node < n;

    const float2* u2 = (const float2*)u;
    float bav = ba[lane];   // hoisted
    float bbv = bb[lane];   // hoisted

    int cnt = 0;
    float2 acc = make_float2(0.0f, 0.0f);
    if (alive) {
        int rs = g_rowstart[node];
        cnt = g_cnt[node];
        int pc = (cnt + 3) & ~3;
        float2 sv = relu2(u2[node * 16 + sub]);
        float comp = (float)(1 - (pc - cnt));
        acc.x = comp * sv.x;
        acc.y = comp * sv.y;
        for (int j = rs; j < rs + pc; j += 4) {
            int4 e = *(const int4*)(g_adjs + j);
            float2 v0 = relu2(u2[e.x * 16 + sub]);
            float2 v1 = relu2(u2[e.y * 16 + sub]);
            float2 v2 = relu2(u2[e.z * 16 + sub]);
            float2 v3 = relu2(u2[e.w * 16 + sub]);
            acc.x += (v0.x + v1.x) + (v2.x + v3.x);
            acc.y += (v0.y + v1.y) + (v2.y + v3.y);
        }
    }

    int wslot = (tid >> 5) * 64;
    *(float2*)(sT + wslot + half * 32 + 2 * sub) = acc;
    __syncwarp();

    int warp2 = warp * 2;
#pragma unroll
    for (int h = 0; h < 2; h++) {
        int nd = warp2 + h;
        if (nd >= n) break;
        int cn = __shfl_sync(0xFFFFFFFFu, cnt, h << 4);
        float dis = rsqrtf((float)(cn + 1));
        const float4* t4p = (const float4*)(sT + wslot + h * 32);
        const float* wra = sWta + lane * 36;
        const float* wrb = sWtb + lane * 36;
        float sa = 0.0f, sb = 0.0f;
#pragma unroll
        for (int q = 0; q < 8; q++) {
            float4 t4 = t4p[q];
            float4 wa = *(const float4*)(wra + 4 * q);
            float4 wb = *(const float4*)(wrb + 4 * q);
            sa += t4.x * wa.x + t4.y * wa.y;
            sa += t4.z * wa.z + t4.w * wa.w;
            sb += t4.x * wb.x + t4.y * wb.y;
            sb += t4.z * wb.z + t4.w * wb.w;
        }
        oa[nd * 32 + lane] = bav + dis * sa;
        ob[nd * 32 + lane] = bbv + dis * sb;
    }
}

// ---------------------------------------------------------------------------
// Launch
// ---------------------------------------------------------------------------

static inline int cdiv(long long a, int b) { return (int)((a + b - 1) / b); }

extern "C" void kernel_launch(void* const* d_in, const int* in_sizes, int n_in,
                              void* d_out, int out_size)
{
    const float* x   = (const float*)d_in[0];
    const void*  ei  = d_in[1];
    const float* W1  = (const float*)d_in[2];
    const float* b1  = (const float*)d_in[3];
    const float* W2  = (const float*)d_in[4];
    const float* b2  = (const float*)d_in[5];
    const float* Wmu = (const float*)d_in[6];
    const float* bmu = (const float*)d_in[7];
    const float* Wlv = (const float*)d_in[8];
    const float* blv = (const float*)d_in[9];

    int N = in_sizes[0] / 32;
    int E = in_sizes[1] / 2;

    float* mu = (float*)d_out;
    float* lv = mu + (size_t)N * 32;

    float* bufA; float* bufB;
    cudaGetSymbolAddress((void**)&bufA, g_bufA);
    cudaGetSymbolAddress((void**)&bufB, g_bufB);

    const int T = 256;
    int gN  = cdiv(N, T);                  // per-node
    int gE  = cdiv(E, T);                  // per-edge
    int gE4 = cdiv(E, T * 4);              // 4 edges per thread
    int gP  = cdiv((long long)N * 16, T);  // per-float2
    int gH  = cdiv((long long)N * 16, T);  // half-warp-per-node (layers)

    // CSR build (src-only payload, x4 self-padded rows) + layer-1 pre-scale
    k_init<<<gN, T>>>((const int*)ei, E, N);
    k_count<<<gE4, T>>>(ei, E);
    k_rowalloc<<<gN, T>>>(N);
    k_prescale<<<gP, T>>>(x, bufA, N);
    k_permute<<<gE, T>>>(ei, E);

    // Layer 1: u2 = dis (.) ((A u1) @ W1 + b1)
    k_layer<0, 1><<<gH, T>>>(bufA, W1, b1, bufB, N);
    // Layer 2: u3 = dis (.) ((A r(u2)) @ W2 + b2)
    k_layer<1, 1><<<gH, T>>>(bufB, W2, b2, bufA, N);
    // Heads: t = A r(u3); mu = dis*(t@Wmu) + bmu; lv = dis*(t@Wlv) + blv
    k_layer2<<<gH, T>>>(bufA, Wmu, Wlv, bmu, blv, mu, lv, N);
}

// round 15
// speedup vs baseline: 1.5753x; 1.0640x over previous
#include <cuda_runtime.h>
#include <cuda_bf16.h>

// VGAE encoder, pull-based, rank-1 norm factored out:
//   norm_ij = dis_i*dis_j  =>  out_i = dis_i * (u_i + sum_{j in N(i)} u_j),  u = dis (.) h.
// Activations stored pre-scaled by dis (relu commutes, dis>0); CSR payload src-only.
// Rows padded to x4 with self-index (compensated in acc init) -> divergence-free
// int4 gather loops. Layers: QUARTER-WARP per node (4 nodes per warp, 4 concurrent
// gather chains; lane holds a float4 channel-quad) + smem GEMV epilogue.
// CRITICAL: g_alloc atomic stays thread-per-node (32 same-address atomics/warp)
// so ptxas warp-aggregates it; single-lane form costs ~60us serialized atomics.

#define N_MAX 131072
#define E_MAX 2097152   // >= E + 3*N (per-node padding to 4)

// Scratch (device globals; no allocations allowed)
__device__ int   g_is64;
__device__ int   g_alloc;            // CSR region allocator
__device__ int   g_cnt[N_MAX];       // in-degree (excluding self-loop)
__device__ int   g_rowstart[N_MAX];
__device__ int   g_cur[N_MAX];       // permutation cursor
__device__ float g_dis[N_MAX];       // deg^-1/2 (deg includes self-loop)
__device__ int   g_adjs[E_MAX];      // CSR payload: src only (padded with self)
__device__ float g_bufA[(size_t)N_MAX * 32];
__device__ float g_bufB[(size_t)N_MAX * 32];

// ---------------------------------------------------------------------------
// Init: zero g_cnt (all blocks); block 0 also detects edge dtype.
// ---------------------------------------------------------------------------

__global__ __launch_bounds__(256) void k_init(const int* __restrict__ ei32,
                                              int E, int n) {
    int i = blockIdx.x * blockDim.x + threadIdx.x;
    if (i < n) g_cnt[i] = 0;
    if (blockIdx.x == 0) {
        int t = threadIdx.x;
        int n_check = 256 < E ? 256 : E;
        int nz = (t < n_check && ei32[2 * t + 1] != 0) ? 1 : 0;
        int any = __syncthreads_or(nz);
        if (t == 0) {
            g_is64 = !any;
            g_alloc = 0;
        }
    }
}

// Count in-degrees, 4 edges per thread (vectorized loads).
__global__ __launch_bounds__(256) void k_count(const void* __restrict__ eiv, int E) {
    int t = blockIdx.x * blockDim.x + threadIdx.x;
    int e0 = t * 4;
    if (e0 >= E) return;
    int d[4];
    int m = (E - e0 < 4) ? (E - e0) : 4;
    if (g_is64) {
        const long long* ei = (const long long*)eiv + (size_t)E + e0;
        if (m == 4) {
            longlong2 a = ((const longlong2*)ei)[0];
            longlong2 b = ((const longlong2*)ei)[1];
            d[0] = (int)a.x; d[1] = (int)a.y; d[2] = (int)b.x; d[3] = (int)b.y;
        } else {
            for (int k = 0; k < m; k++) d[k] = (int)ei[k];
        }
    } else {
        const int* ei = (const int*)eiv + (size_t)E + e0;
        if (m == 4) {
            int4 a = *(const int4*)ei;
            d[0] = a.x; d[1] = a.y; d[2] = a.z; d[3] = a.w;
        } else {
            for (int k = 0; k < m; k++) d[k] = ei[k];
        }
    }
    for (int k = 0; k < m; k++) atomicAdd(&g_cnt[d[k]], 1);
}

// Atomic CSR region allocation (thread-per-node => ptxas warp-aggregates the
// same-address atomic). Pads rows to x4 with the node's own index.
__global__ void k_rowalloc(int n) {
    int i = blockIdx.x * blockDim.x + threadIdx.x;
    if (i >= n) return;
    int c = g_cnt[i];
    int pc = (c + 3) & ~3;
    int rs = atomicAdd(&g_alloc, pc);
    g_rowstart[i] = rs;
    g_cur[i] = rs;
    g_dis[i] = rsqrtf((float)(c + 1));  // +1 self-loop
    for (int k = c; k < pc; k++) g_adjs[rs + k] = i;  // self-index padding
}

// u = dis (.) x  (layer-1 input pre-scale)
__global__ __launch_bounds__(256) void k_prescale(const float* __restrict__ x,
                                                  float* __restrict__ u, int n) {
    int i = blockIdx.x * blockDim.x + threadIdx.x;
    if (i >= n * 16) return;
    float s = g_dis[i >> 4];
    float2 v = ((const float2*)x)[i];
    v.x *= s; v.y *= s;
    ((float2*)u)[i] = v;
}

// Permute edges into CSR (1 edge per thread).
__global__ void k_permute(const void* __restrict__ eiv, int E) {
    int e = blockIdx.x * blockDim.x + threadIdx.x;
    if (e >= E) return;
    int s, d;
    if (g_is64) {
        const long long* ei = (const long long*)eiv;
        s = (int)ei[e];
        d = (int)ei[(size_t)E + e];
    } else {
        const int* ei = (const int*)eiv;
        s = ei[e];
        d = ei[(size_t)E + e];
    }
    int pos = atomicAdd(&g_cur[d], 1);
    g_adjs[pos] = s;
}

// ---------------------------------------------------------------------------
// Fused layer: QUARTER-WARP per node (node = warp*4 + q, q = lane>>3);
// lane holds channels (4*sub .. 4*sub+3) as float4, sub = lane&7.
//   t = (1-pad)*r(u_i) + sum over padded row of r(u_src)   (pad slots = self)
//   o = b + dis*(t @ W);  out = PRE_OUT ? dis*o : o
// Epilogue: 4 t rows staged to smem; the full warp runs one GEMV per node
// (broadcast t float4s, per-lane transposed-W row, conflict-free pitch 36).
// ---------------------------------------------------------------------------

__device__ __forceinline__ float4 relu4(float4 v) {
    v.x = fmaxf(v.x, 0.0f); v.y = fmaxf(v.y, 0.0f);
    v.z = fmaxf(v.z, 0.0f); v.w = fmaxf(v.w, 0.0f);
    return v;
}

__device__ __forceinline__ void acc4(float4& a, float4 v) {
    a.x += v.x; a.y += v.y; a.z += v.z; a.w += v.w;
}

template <int RELU, int PRE_OUT>
__global__ __launch_bounds__(256) void k_layer(
    const float* __restrict__ u, const float* __restrict__ W,
    const float* __restrict__ b, float* __restrict__ out, int n)
{
    __shared__ float4 sWtv[288];   // W transposed: sWt[j*36 + k] = W[k][j]
    __shared__ float4 sTv[256];    // 8 warps x 4 nodes x 32 floats
    float* sWt = (float*)sWtv;
    float* sT  = (float*)sTv;
    int tid = threadIdx.x;
#pragma unroll
    for (int it = 0; it < 4; it++) {
        int idx = tid + it * 256;
        float w = W[idx];
        int k = idx >> 5, j = idx & 31;
        sWt[j * 36 + k] = w;
    }
    __syncthreads();

    int warp = (blockIdx.x * blockDim.x + tid) >> 5;
    int lane = tid & 31;
    int q    = lane >> 3;      // quarter 0..3
    int sub  = lane & 7;       // channel quad index
    int node = warp * 4 + q;
    bool alive = node < n;

    const float4* u4 = (const float4*)u;
    float bv = b[lane];        // hoisted off the epilogue's dependent chain

    int cnt = 0;
    float4 acc = make_float4(0.0f, 0.0f, 0.0f, 0.0f);
    if (alive) {
        int rs = g_rowstart[node];
        cnt = g_cnt[node];
        int pc = (cnt + 3) & ~3;
        float4 sv = u4[node * 8 + sub];
        if (RELU) sv = relu4(sv);
        float comp = (float)(1 - (pc - cnt));
        acc.x = comp * sv.x; acc.y = comp * sv.y;
        acc.z = comp * sv.z; acc.w = comp * sv.w;
        for (int j = rs; j < rs + pc; j += 4) {
            int4 e = *(const int4*)(g_adjs + j);
            float4 v0 = u4[e.x * 8 + sub];
            float4 v1 = u4[e.y * 8 + sub];
            float4 v2 = u4[e.z * 8 + sub];
            float4 v3 = u4[e.w * 8 + sub];
            if (RELU) { v0 = relu4(v0); v1 = relu4(v1); v2 = relu4(v2); v3 = relu4(v3); }
            acc4(acc, v0); acc4(acc, v1); acc4(acc, v2); acc4(acc, v3);
        }
    }

    // stage all 4 nodes' t rows
    int wslot = (tid >> 5) * 128;
    *(float4*)(sT + wslot + q * 32 + 4 * sub) = acc;
    __syncwarp();

    // four full-warp GEMVs, one per node
    int warp4 = warp * 4;
    const float* wr = sWt + lane * 36;
#pragma unroll
    for (int h = 0; h < 4; h++) {
        int nd = warp4 + h;
        if (nd >= n) break;
        int cn = __shfl_sync(0xFFFFFFFFu, cnt, h << 3);
        float dis = rsqrtf((float)(cn + 1));
        const float4* t4p = (const float4*)(sT + wslot + h * 32);
        float s = 0.0f;
#pragma unroll
        for (int p = 0; p < 8; p++) {
            float4 t4 = t4p[p];
            float4 w4 = *(const float4*)(wr + 4 * p);
            s += t4.x * w4.x + t4.y * w4.y;
            s += t4.z * w4.z + t4.w * w4.w;
        }
        float sb = PRE_OUT ? dis : 1.0f;
        float ss = PRE_OUT ? dis * dis : dis;
        out[nd * 32 + lane] = sb * bv + ss * s;
    }
}

// Fused dual head: one aggregation per node, two smem GEMVs (mu and logvar).
__global__ __launch_bounds__(256) void k_layer2(
    const float* __restrict__ u,
    const float* __restrict__ Wa, const float* __restrict__ Wb,
    const float* __restrict__ ba, const float* __restrict__ bb,
    float* __restrict__ oa, float* __restrict__ ob, int n)
{
    __shared__ float4 sWtav[288];
    __shared__ float4 sWtbv[288];
    __shared__ float4 sTv[256];
    float* sWta = (float*)sWtav;
    float* sWtb = (float*)sWtbv;
    float* sT   = (float*)sTv;
    int tid = threadIdx.x;
#pragma unroll
    for (int it = 0; it < 4; it++) {
        int idx = tid + it * 256;
        float wa = Wa[idx];
        float wb = Wb[idx];
        int k = idx >> 5, j = idx & 31;
        sWta[j * 36 + k] = wa;
        sWtb[j * 36 + k] = wb;
    }
    __syncthreads();

    int warp = (blockIdx.x * blockDim.x + tid) >> 5;
    int lane = tid & 31;
    int q    = lane >> 3;
    int sub  = lane & 7;
    int node = warp * 4 + q;
    bool alive = node < n;

    const float4* u4 = (const float4*)u;
    float bav = ba[lane];   // hoisted
    float bbv = bb[lane];   // hoisted

    int cnt = 0;
    float4 acc = make_float4(0.0f, 0.0f, 0.0f, 0.0f);
    if (alive) {
        int rs = g_rowstart[node];
        cnt = g_cnt[node];
        int pc = (cnt + 3) & ~3;
        float4 sv = relu4(u4[node * 8 + sub]);
        float comp = (float)(1 - (pc - cnt));
        acc.x = comp * sv.x; acc.y = comp * sv.y;
        acc.z = comp * sv.z; acc.w = comp * sv.w;
        for (int j = rs; j < rs + pc; j += 4) {
            int4 e = *(const int4*)(g_adjs + j);
            float4 v0 = relu4(u4[e.x * 8 + sub]);
            float4 v1 = relu4(u4[e.y * 8 + sub]);
            float4 v2 = relu4(u4[e.z * 8 + sub]);
            float4 v3 = relu4(u4[e.w * 8 + sub]);
            acc4(acc, v0); acc4(acc, v1); acc4(acc, v2); acc4(acc, v3);
        }
    }

    int wslot = (tid >> 5) * 128;
    *(float4*)(sT + wslot + q * 32 + 4 * sub) = acc;
    __syncwarp();

    int warp4 = warp * 4;
    const float* wra = sWta + lane * 36;
    const float* wrb = sWtb + lane * 36;
#pragma unroll
    for (int h = 0; h < 4; h++) {
        int nd = warp4 + h;
        if (nd >= n) break;
        int cn = __shfl_sync(0xFFFFFFFFu, cnt, h << 3);
        float dis = rsqrtf((float)(cn + 1));
        const float4* t4p = (const float4*)(sT + wslot + h * 32);
        float sa = 0.0f, sb = 0.0f;
#pragma unroll
        for (int p = 0; p < 8; p++) {
            float4 t4 = t4p[p];
            float4 wa = *(const float4*)(wra + 4 * p);
            float4 wb = *(const float4*)(wrb + 4 * p);
            sa += t4.x * wa.x + t4.y * wa.y;
            sa += t4.z * wa.z + t4.w * wa.w;
            sb += t4.x * wb.x + t4.y * wb.y;
            sb += t4.z * wb.z + t4.w * wb.w;
        }
        oa[nd * 32 + lane] = bav + dis * sa;
        ob[nd * 32 + lane] = bbv + dis * sb;
    }
}

// ---------------------------------------------------------------------------
// Launch
// ---------------------------------------------------------------------------

static inline int cdiv(long long a, int b) { return (int)((a + b - 1) / b); }

extern "C" void kernel_launch(void* const* d_in, const int* in_sizes, int n_in,
                              void* d_out, int out_size)
{
    const float* x   = (const float*)d_in[0];
    const void*  ei  = d_in[1];
    const float* W1  = (const float*)d_in[2];
    const float* b1  = (const float*)d_in[3];
    const float* W2  = (const float*)d_in[4];
    const float* b2  = (const float*)d_in[5];
    const float* Wmu = (const float*)d_in[6];
    const float* bmu = (const float*)d_in[7];
    const float* Wlv = (const float*)d_in[8];
    const float* blv = (const float*)d_in[9];

    int N = in_sizes[0] / 32;
    int E = in_sizes[1] / 2;

    float* mu = (float*)d_out;
    float* lv = mu + (size_t)N * 32;

    float* bufA; float* bufB;
    cudaGetSymbolAddress((void**)&bufA, g_bufA);
    cudaGetSymbolAddress((void**)&bufB, g_bufB);

    const int T = 256;
    int gN  = cdiv(N, T);                  // per-node
    int gE  = cdiv(E, T);                  // per-edge
    int gE4 = cdiv(E, T * 4);              // 4 edges per thread
    int gP  = cdiv((long long)N * 16, T);  // per-float2
    int gQ  = cdiv((long long)N * 8, T);   // quarter-warp-per-node (layers)

    // CSR build (src-only payload, x4 self-padded rows) + layer-1 pre-scale
    k_init<<<gN, T>>>((const int*)ei, E, N);
    k_count<<<gE4, T>>>(ei, E);
    k_rowalloc<<<gN, T>>>(N);
    k_prescale<<<gP, T>>>(x, bufA, N);
    k_permute<<<gE, T>>>(ei, E);

    // Layer 1: u2 = dis (.) ((A u1) @ W1 + b1)
    k_layer<0, 1><<<gQ, T>>>(bufA, W1, b1, bufB, N);
    // Layer 2: u3 = dis (.) ((A r(u2)) @ W2 + b2)
    k_layer<1, 1><<<gQ, T>>>(bufB, W2, b2, bufA, N);
    // Heads: t = A r(u3); mu = dis*(t@Wmu) + bmu; lv = dis*(t@Wlv) + blv
    k_layer2<<<gQ, T>>>(bufA, Wmu, Wlv, bmu, blv, mu, lv, N);
}

// round 16
// speedup vs baseline: 1.7088x; 1.0848x over previous
#include <cuda_runtime.h>
#include <cuda_bf16.h>

// VGAE encoder, pull-based, rank-1 norm factored out:
//   norm_ij = dis_i*dis_j  =>  out_i = dis_i * (u_i + sum_{j in N(i)} u_j),  u = dis (.) h.
// Activations stored pre-scaled by dis (relu commutes, dis>0); CSR payload src-only.
// Rows padded to x4 with self-index (compensated in acc init) -> divergence-free
// int4 gather loops. Layers: EIGHTH-WARP per node (8 nodes per warp, 8 concurrent
// gather chains; 4 lanes/node, each lane holds 8 channels as 2x float4) + smem
// GEMV epilogue (transposed W, float4 loads).
// CRITICAL: the g_alloc atomic is issued by ALL 32 lanes of fully-active warps
// (thread-per-node on a dense grid) so ptxas warp-aggregates it; a single-lane
// form costs ~60us of serialized same-address L2 atomics (measured r13).

#define N_MAX 131072
#define E_MAX 2097152   // >= E + 3*N (per-node padding to 4)

// Scratch (device globals; no allocations allowed)
__device__ int   g_is64;
__device__ int   g_alloc;            // CSR region allocator
__device__ int   g_cnt[N_MAX];       // in-degree (excluding self-loop)
__device__ int   g_rowstart[N_MAX];
__device__ int   g_cur[N_MAX];       // permutation cursor
__device__ int   g_adjs[E_MAX];      // CSR payload: src only (padded with self)
__device__ float g_bufA[(size_t)N_MAX * 32];
__device__ float g_bufB[(size_t)N_MAX * 32];

// ---------------------------------------------------------------------------
// Init: zero g_cnt (all blocks); block 0 also detects edge dtype.
// ---------------------------------------------------------------------------

__global__ __launch_bounds__(256) void k_init(const int* __restrict__ ei32,
                                              int E, int n) {
    int i = blockIdx.x * blockDim.x + threadIdx.x;
    if (i < n) g_cnt[i] = 0;
    if (blockIdx.x == 0) {
        int t = threadIdx.x;
        int n_check = 256 < E ? 256 : E;
        int nz = (t < n_check && ei32[2 * t + 1] != 0) ? 1 : 0;
        int any = __syncthreads_or(nz);
        if (t == 0) {
            g_is64 = !any;
            g_alloc = 0;
        }
    }
}

// Count in-degrees, 4 edges per thread (vectorized loads).
__global__ __launch_bounds__(256) void k_count(const void* __restrict__ eiv, int E) {
    int t = blockIdx.x * blockDim.x + threadIdx.x;
    int e0 = t * 4;
    if (e0 >= E) return;
    int d[4];
    int m = (E - e0 < 4) ? (E - e0) : 4;
    if (g_is64) {
        const long long* ei = (const long long*)eiv + (size_t)E + e0;
        if (m == 4) {
            longlong2 a = ((const longlong2*)ei)[0];
            longlong2 b = ((const longlong2*)ei)[1];
            d[0] = (int)a.x; d[1] = (int)a.y; d[2] = (int)b.x; d[3] = (int)b.y;
        } else {
            for (int k = 0; k < m; k++) d[k] = (int)ei[k];
        }
    } else {
        const int* ei = (const int*)eiv + (size_t)E + e0;
        if (m == 4) {
            int4 a = *(const int4*)ei;
            d[0] = a.x; d[1] = a.y; d[2] = a.z; d[3] = a.w;
        } else {
            for (int k = 0; k < m; k++) d[k] = ei[k];
        }
    }
    for (int k = 0; k < m; k++) atomicAdd(&g_cnt[d[k]], 1);
}

// CSR region allocation fused with layer-1 pre-scale, on the N*8 grid.
// Threads < n: thread-per-node alloc (fully-active warps => the same-address
// g_alloc atomic stays warp-aggregated by ptxas) + x4 self-index row padding.
// All threads < n*8: one float4 of u1 = dis (.) x, with dis recomputed from
// g_cnt (no cross-block dependency on alloc results).
__global__ __launch_bounds__(256) void k_rowalloc(const float* __restrict__ x,
                                                  float* __restrict__ u, int n) {
    int t = blockIdx.x * blockDim.x + threadIdx.x;
    if (t < n) {
        int c = g_cnt[t];
        int pc = (c + 3) & ~3;
        int rs = atomicAdd(&g_alloc, pc);
        g_rowstart[t] = rs;
        g_cur[t] = rs;
        for (int k = c; k < pc; k++) g_adjs[rs + k] = t;  // self-index padding
    }
    if (t < n * 8) {
        int node = t >> 3;
        float dis = rsqrtf((float)(g_cnt[node] + 1));  // +1 self-loop
        float4 v = ((const float4*)x)[t];
        v.x *= dis; v.y *= dis; v.z *= dis; v.w *= dis;
        ((float4*)u)[t] = v;
    }
}

// Permute edges into CSR (1 edge per thread).
__global__ void k_permute(const void* __restrict__ eiv, int E) {
    int e = blockIdx.x * blockDim.x + threadIdx.x;
    if (e >= E) return;
    int s, d;
    if (g_is64) {
        const long long* ei = (const long long*)eiv;
        s = (int)ei[e];
        d = (int)ei[(size_t)E + e];
    } else {
        const int* ei = (const int*)eiv;
        s = ei[e];
        d = ei[(size_t)E + e];
    }
    int pos = atomicAdd(&g_cur[d], 1);
    g_adjs[pos] = s;
}

// ---------------------------------------------------------------------------
// Fused layer: EIGHTH-WARP per node (node = warp*8 + oct, oct = lane>>2);
// lane holds channels (4*sub..4*sub+3) and (16+4*sub..16+4*sub+3), sub = lane&3.
//   t = (1-pad)*r(u_i) + sum over padded row of r(u_src)   (pad slots = self)
//   o = b + dis*(t @ W);  out = PRE_OUT ? dis*o : o
// Epilogue: 8 t rows staged to smem; the full warp runs one GEMV per node
// (broadcast t float4s, per-lane transposed-W row, conflict-free pitch 36).
// ---------------------------------------------------------------------------

__device__ __forceinline__ float4 relu4(float4 v) {
    v.x = fmaxf(v.x, 0.0f); v.y = fmaxf(v.y, 0.0f);
    v.z = fmaxf(v.z, 0.0f); v.w = fmaxf(v.w, 0.0f);
    return v;
}

__device__ __forceinline__ void acc4(float4& a, float4 v) {
    a.x += v.x; a.y += v.y; a.z += v.z; a.w += v.w;
}

template <int RELU, int PRE_OUT>
__global__ __launch_bounds__(256) void k_layer(
    const float* __restrict__ u, const float* __restrict__ W,
    const float* __restrict__ b, float* __restrict__ out, int n)
{
    __shared__ float4 sWtv[288];   // W transposed: sWt[j*36 + k] = W[k][j]
    __shared__ float4 sTv[512];    // 8 warps x 8 nodes x 32 floats
    float* sWt = (float*)sWtv;
    float* sT  = (float*)sTv;
    int tid = threadIdx.x;
#pragma unroll
    for (int it = 0; it < 4; it++) {
        int idx = tid + it * 256;
        float w = W[idx];
        int k = idx >> 5, j = idx & 31;
        sWt[j * 36 + k] = w;
    }
    __syncthreads();

    int warp = (blockIdx.x * blockDim.x + tid) >> 5;
    int lane = tid & 31;
    int oct  = lane >> 2;      // node slot 0..7
    int sub  = lane & 3;       // channel quad index (lo half)
    int node = warp * 8 + oct;
    bool alive = node < n;

    const float4* u4 = (const float4*)u;
    float bv = b[lane];        // hoisted off the epilogue's dependent chain

    int cnt = 0;
    float4 alo = make_float4(0.0f, 0.0f, 0.0f, 0.0f);
    float4 ahi = make_float4(0.0f, 0.0f, 0.0f, 0.0f);
    if (alive) {
        int rs = g_rowstart[node];
        cnt = g_cnt[node];
        int pc = (cnt + 3) & ~3;
        float4 slo = u4[node * 8 + sub];
        float4 shi = u4[node * 8 + 4 + sub];
        if (RELU) { slo = relu4(slo); shi = relu4(shi); }
        float comp = (float)(1 - (pc - cnt));
        alo.x = comp * slo.x; alo.y = comp * slo.y;
        alo.z = comp * slo.z; alo.w = comp * slo.w;
        ahi.x = comp * shi.x; ahi.y = comp * shi.y;
        ahi.z = comp * shi.z; ahi.w = comp * shi.w;
        for (int j = rs; j < rs + pc; j += 4) {
            int4 e = *(const int4*)(g_adjs + j);
            float4 v0 = u4[e.x * 8 + sub];
            float4 w0 = u4[e.x * 8 + 4 + sub];
            float4 v1 = u4[e.y * 8 + sub];
            float4 w1 = u4[e.y * 8 + 4 + sub];
            float4 v2 = u4[e.z * 8 + sub];
            float4 w2 = u4[e.z * 8 + 4 + sub];
            float4 v3 = u4[e.w * 8 + sub];
            float4 w3 = u4[e.w * 8 + 4 + sub];
            if (RELU) {
                v0 = relu4(v0); w0 = relu4(w0); v1 = relu4(v1); w1 = relu4(w1);
                v2 = relu4(v2); w2 = relu4(w2); v3 = relu4(v3); w3 = relu4(w3);
            }
            acc4(alo, v0); acc4(alo, v1); acc4(alo, v2); acc4(alo, v3);
            acc4(ahi, w0); acc4(ahi, w1); acc4(ahi, w2); acc4(ahi, w3);
        }
    }

    // stage all 8 nodes' t rows
    int wslot = (tid >> 5) * 256;
    *(float4*)(sT + wslot + oct * 32 + 4 * sub) = alo;
    *(float4*)(sT + wslot + oct * 32 + 16 + 4 * sub) = ahi;
    __syncwarp();

    // eight full-warp GEMVs, one per node
    int warp8 = warp * 8;
    const float* wr = sWt + lane * 36;
#pragma unroll
    for (int h = 0; h < 8; h++) {
        int nd = warp8 + h;
        if (nd >= n) break;
        int cn = __shfl_sync(0xFFFFFFFFu, cnt, h << 2);
        float dis = rsqrtf((float)(cn + 1));
        const float4* t4p = (const float4*)(sT + wslot + h * 32);
        float s = 0.0f;
#pragma unroll
        for (int p = 0; p < 8; p++) {
            float4 t4 = t4p[p];
            float4 w4 = *(const float4*)(wr + 4 * p);
            s += t4.x * w4.x + t4.y * w4.y;
            s += t4.z * w4.z + t4.w * w4.w;
        }
        float sb = PRE_OUT ? dis : 1.0f;
        float ss = PRE_OUT ? dis * dis : dis;
        out[nd * 32 + lane] = sb * bv + ss * s;
    }
}

// Fused dual head: one aggregation per node, two smem GEMVs (mu and logvar).
__global__ __launch_bounds__(256) void k_layer2(
    const float* __restrict__ u,
    const float* __restrict__ Wa, const float* __restrict__ Wb,
    const float* __restrict__ ba, const float* __restrict__ bb,
    float* __restrict__ oa, float* __restrict__ ob, int n)
{
    __shared__ float4 sWtav[288];
    __shared__ float4 sWtbv[288];
    __shared__ float4 sTv[512];
    float* sWta = (float*)sWtav;
    float* sWtb = (float*)sWtbv;
    float* sT   = (float*)sTv;
    int tid = threadIdx.x;
#pragma unroll
    for (int it = 0; it < 4; it++) {
        int idx = tid + it * 256;
        float wa = Wa[idx];
        float wb = Wb[idx];
        int k = idx >> 5, j = idx & 31;
        sWta[j * 36 + k] = wa;
        sWtb[j * 36 + k] = wb;
    }
    __syncthreads();

    int warp = (blockIdx.x * blockDim.x + tid) >> 5;
    int lane = tid & 31;
    int oct  = lane >> 2;
    int sub  = lane & 3;
    int node = warp * 8 + oct;
    bool alive = node < n;

    const float4* u4 = (const float4*)u;
    float bav = ba[lane];   // hoisted
    float bbv = bb[lane];   // hoisted

    int cnt = 0;
    float4 alo = make_float4(0.0f, 0.0f, 0.0f, 0.0f);
    float4 ahi = make_float4(0.0f, 0.0f, 0.0f, 0.0f);
    if (alive) {
        int rs = g_rowstart[node];
        cnt = g_cnt[node];
        int pc = (cnt + 3) & ~3;
        float4 slo = relu4(u4[node * 8 + sub]);
        float4 shi = relu4(u4[node * 8 + 4 + sub]);
        float comp = (float)(1 - (pc - cnt));
        alo.x = comp * slo.x; alo.y = comp * slo.y;
        alo.z = comp * slo.z; alo.w = comp * slo.w;
        ahi.x = comp * shi.x; ahi.y = comp * shi.y;
        ahi.z = comp * shi.z; ahi.w = comp * shi.w;
        for (int j = rs; j < rs + pc; j += 4) {
            int4 e = *(const int4*)(g_adjs + j);
            float4 v0 = relu4(u4[e.x * 8 + sub]);
            float4 w0 = relu4(u4[e.x * 8 + 4 + sub]);
            float4 v1 = relu4(u4[e.y * 8 + sub]);
            float4 w1 = relu4(u4[e.y * 8 + 4 + sub]);
            float4 v2 = relu4(u4[e.z * 8 + sub]);
            float4 w2 = relu4(u4[e.z * 8 + 4 + sub]);
            float4 v3 = relu4(u4[e.w * 8 + sub]);
            float4 w3 = relu4(u4[e.w * 8 + 4 + sub]);
            acc4(alo, v0); acc4(alo, v1); acc4(alo, v2); acc4(alo, v3);
            acc4(ahi, w0); acc4(ahi, w1); acc4(ahi, w2); acc4(ahi, w3);
        }
    }

    int wslot = (tid >> 5) * 256;
    *(float4*)(sT + wslot + oct * 32 + 4 * sub) = alo;
    *(float4*)(sT + wslot + oct * 32 + 16 + 4 * sub) = ahi;
    __syncwarp();

    int warp8 = warp * 8;
    const float* wra = sWta + lane * 36;
    const float* wrb = sWtb + lane * 36;
#pragma unroll
    for (int h = 0; h < 8; h++) {
        int nd = warp8 + h;
        if (nd >= n) break;
        int cn = __shfl_sync(0xFFFFFFFFu, cnt, h << 2);
        float dis = rsqrtf((float)(cn + 1));
        const float4* t4p = (const float4*)(sT + wslot + h * 32);
        float sa = 0.0f, sb = 0.0f;
#pragma unroll
        for (int p = 0; p < 8; p++) {
            float4 t4 = t4p[p];
            float4 wa = *(const float4*)(wra + 4 * p);
            float4 wb = *(const float4*)(wrb + 4 * p);
            sa += t4.x * wa.x + t4.y * wa.y;
            sa += t4.z * wa.z + t4.w * wa.w;
            sb += t4.x * wb.x + t4.y * wb.y;
            sb += t4.z * wb.z + t4.w * wb.w;
        }
        oa[nd * 32 + lane] = bav + dis * sa;
        ob[nd * 32 + lane] = bbv + dis * sb;
    }
}

// ---------------------------------------------------------------------------
// Launch
// ---------------------------------------------------------------------------

static inline int cdiv(long long a, int b) { return (int)((a + b - 1) / b); }

extern "C" void kernel_launch(void* const* d_in, const int* in_sizes, int n_in,
                              void* d_out, int out_size)
{
    const float* x   = (const float*)d_in[0];
    const void*  ei  = d_in[1];
    const float* W1  = (const float*)d_in[2];
    const float* b1  = (const float*)d_in[3];
    const float* W2  = (const float*)d_in[4];
    const float* b2  = (const float*)d_in[5];
    const float* Wmu = (const float*)d_in[6];
    const float* bmu = (const float*)d_in[7];
    const float* Wlv = (const float*)d_in[8];
    const float* blv = (const float*)d_in[9];

    int N = in_sizes[0] / 32;
    int E = in_sizes[1] / 2;

    float* mu = (float*)d_out;
    float* lv = mu + (size_t)N * 32;

    float* bufA; float* bufB;
    cudaGetSymbolAddress((void**)&bufA, g_bufA);
    cudaGetSymbolAddress((void**)&bufB, g_bufB);

    const int T = 256;
    int gN  = cdiv(N, T);                  // per-node
    int gE  = cdiv(E, T);                  // per-edge
    int gE4 = cdiv(E, T * 4);              // 4 edges per thread
    int gP  = cdiv((long long)N * 8, T);   // per-float4 (rowalloc+prescale grid)
    int gO  = cdiv((long long)N * 4, T);   // eighth-warp-per-node (layers)

    // CSR build (src-only payload, x4 self-padded rows); rowalloc fused with
    // layer-1 pre-scale on the dense grid (preserves warp-aggregated atomic).
    k_init<<<gN, T>>>((const int*)ei, E, N);
    k_count<<<gE4, T>>>(ei, E);
    k_rowalloc<<<gP, T>>>(x, bufA, N);
    k_permute<<<gE, T>>>(ei, E);

    // Layer 1: u2 = dis (.) ((A u1) @ W1 + b1)
    k_layer<0, 1><<<gO, T>>>(bufA, W1, b1, bufB, N);
    // Layer 2: u3 = dis (.) ((A r(u2)) @ W2 + b2)
    k_layer<1, 1><<<gO, T>>>(bufB, W2, b2, bufA, N);
    // Heads: t = A r(u3); mu = dis*(t@Wmu) + bmu; lv = dis*(t@Wlv) + blv
    k_layer2<<<gO, T>>>(bufA, Wmu, Wlv, bmu, blv, mu, lv, N);
}

// round 17
// speedup vs baseline: 1.7817x; 1.0427x over previous
#include <cuda_runtime.h>
#include <cuda_bf16.h>

// VGAE encoder, pull-based, rank-1 norm factored out:
//   norm_ij = dis_i*dis_j  =>  out_i = dis_i * (u_i + sum_{j in N(i)} u_j),  u = dis (.) h.
// RELU HOISTED TO PRODUCER: relu(dis (.) a) = dis (.) relu(a) exactly (dis>0), so
// layers 1-2 store relu'd pre-scaled activations and ALL gather loops are pure
// load+add (no per-edge relu). Accumulation uses packed add.rn.f32x2 (sm_103a).
// CSR payload src-only; rows padded to x4 with self-index (compensated in acc
// init) -> divergence-free int4 gather loops. Layers: EIGHTH-WARP per node
// (8 nodes/warp, 8 concurrent gather chains; 4 lanes/node, 8 channels/lane).
// CRITICAL: the g_alloc atomic is issued by ALL 32 lanes of fully-active warps
// (thread-per-node on a dense grid) so ptxas warp-aggregates it; a single-lane
// form costs ~60us of serialized same-address L2 atomics (measured r13).

#define N_MAX 131072
#define E_MAX 2097152   // >= E + 3*N (per-node padding to 4)

// Scratch (device globals; no allocations allowed)
__device__ int   g_is64;
__device__ int   g_alloc;            // CSR region allocator
__device__ int   g_cnt[N_MAX];       // in-degree (excluding self-loop)
__device__ int   g_rowstart[N_MAX];
__device__ int   g_cur[N_MAX];       // permutation cursor
__device__ int   g_adjs[E_MAX];      // CSR payload: src only (padded with self)
__device__ float g_bufA[(size_t)N_MAX * 32];
__device__ float g_bufB[(size_t)N_MAX * 32];

// ---------------------------------------------------------------------------
// Packed f32x2 helpers (ptxas will not auto-fuse scalar FADD pairs).
// ---------------------------------------------------------------------------

__device__ __forceinline__ void addx2(unsigned long long& a, unsigned long long b) {
    asm("add.rn.f32x2 %0, %0, %1;" : "+l"(a) : "l"(b));
}
__device__ __forceinline__ unsigned long long mulx2(unsigned long long a,
                                                    unsigned long long b) {
    unsigned long long r;
    asm("mul.rn.f32x2 %0, %1, %2;" : "=l"(r) : "l"(a), "l"(b));
    return r;
}
__device__ __forceinline__ unsigned long long bcast2(float f) {
    unsigned long long r;
    asm("mov.b64 %0, {%1, %1};" : "=l"(r) : "f"(f));
    return r;
}

// ---------------------------------------------------------------------------
// Init: zero g_cnt (all blocks); block 0 also detects edge dtype.
// ---------------------------------------------------------------------------

__global__ __launch_bounds__(256) void k_init(const int* __restrict__ ei32,
                                              int E, int n) {
    int i = blockIdx.x * blockDim.x + threadIdx.x;
    if (i < n) g_cnt[i] = 0;
    if (blockIdx.x == 0) {
        int t = threadIdx.x;
        int n_check = 256 < E ? 256 : E;
        int nz = (t < n_check && ei32[2 * t + 1] != 0) ? 1 : 0;
        int any = __syncthreads_or(nz);
        if (t == 0) {
            g_is64 = !any;
            g_alloc = 0;
        }
    }
}

// Count in-degrees, 4 edges per thread (vectorized loads).
__global__ __launch_bounds__(256) void k_count(const void* __restrict__ eiv, int E) {
    int t = blockIdx.x * blockDim.x + threadIdx.x;
    int e0 = t * 4;
    if (e0 >= E) return;
    int d[4];
    int m = (E - e0 < 4) ? (E - e0) : 4;
    if (g_is64) {
        const long long* ei = (const long long*)eiv + (size_t)E + e0;
        if (m == 4) {
            longlong2 a = ((const longlong2*)ei)[0];
            longlong2 b = ((const longlong2*)ei)[1];
            d[0] = (int)a.x; d[1] = (int)a.y; d[2] = (int)b.x; d[3] = (int)b.y;
        } else {
            for (int k = 0; k < m; k++) d[k] = (int)ei[k];
        }
    } else {
        const int* ei = (const int*)eiv + (size_t)E + e0;
        if (m == 4) {
            int4 a = *(const int4*)ei;
            d[0] = a.x; d[1] = a.y; d[2] = a.z; d[3] = a.w;
        } else {
            for (int k = 0; k < m; k++) d[k] = ei[k];
        }
    }
    for (int k = 0; k < m; k++) atomicAdd(&g_cnt[d[k]], 1);
}

// CSR region allocation fused with layer-1 pre-scale, on the N*8 grid.
// Threads < n: thread-per-node alloc (fully-active warps => the same-address
// g_alloc atomic stays warp-aggregated by ptxas) + x4 self-index row padding.
// All threads < n*8: one float4 of u1 = dis (.) x (no relu: layer 1 input).
__global__ __launch_bounds__(256) void k_rowalloc(const float* __restrict__ x,
                                                  float* __restrict__ u, int n) {
    int t = blockIdx.x * blockDim.x + threadIdx.x;
    if (t < n) {
        int c = g_cnt[t];
        int pc = (c + 3) & ~3;
        int rs = atomicAdd(&g_alloc, pc);
        g_rowstart[t] = rs;
        g_cur[t] = rs;
        for (int k = c; k < pc; k++) g_adjs[rs + k] = t;  // self-index padding
    }
    if (t < n * 8) {
        int node = t >> 3;
        float dis = rsqrtf((float)(g_cnt[node] + 1));  // +1 self-loop
        float4 v = ((const float4*)x)[t];
        v.x *= dis; v.y *= dis; v.z *= dis; v.w *= dis;
        ((float4*)u)[t] = v;
    }
}

// Permute edges into CSR (1 edge per thread).
__global__ void k_permute(const void* __restrict__ eiv, int E) {
    int e = blockIdx.x * blockDim.x + threadIdx.x;
    if (e >= E) return;
    int s, d;
    if (g_is64) {
        const long long* ei = (const long long*)eiv;
        s = (int)ei[e];
        d = (int)ei[(size_t)E + e];
    } else {
        const int* ei = (const int*)eiv;
        s = ei[e];
        d = ei[(size_t)E + e];
    }
    int pos = atomicAdd(&g_cur[d], 1);
    g_adjs[pos] = s;
}

// ---------------------------------------------------------------------------
// Fused layer: EIGHTH-WARP per node (node = warp*8 + oct, oct = lane>>2);
// lane holds channels (4*sub..4*sub+3) and (16+4*sub..16+4*sub+3), sub = lane&3.
// Gather is PURE load+packed-add (relu was applied by the producer):
//   t = (1-pad)*u_i + sum over padded row of u_src    (pad slots = self)
//   o = b*dis + dis^2*(t @ W);  out = RELU_OUT ? max(o,0) : o
// Epilogue: 8 t rows staged to smem; the full warp runs one GEMV per node
// (broadcast t float4s, per-lane transposed-W row, conflict-free pitch 36).
// ---------------------------------------------------------------------------

template <int RELU_OUT>
__global__ __launch_bounds__(256) void k_layer(
    const float* __restrict__ u, const float* __restrict__ W,
    const float* __restrict__ b, float* __restrict__ out, int n)
{
    __shared__ float4 sWtv[288];   // W transposed: sWt[j*36 + k] = W[k][j]
    __shared__ float4 sTv[512];    // 8 warps x 8 nodes x 32 floats
    float* sWt = (float*)sWtv;
    float* sT  = (float*)sTv;
    int tid = threadIdx.x;
#pragma unroll
    for (int it = 0; it < 4; it++) {
        int idx = tid + it * 256;
        float w = W[idx];
        int k = idx >> 5, j = idx & 31;
        sWt[j * 36 + k] = w;
    }
    __syncthreads();

    int warp = (blockIdx.x * blockDim.x + tid) >> 5;
    int lane = tid & 31;
    int oct  = lane >> 2;      // node slot 0..7
    int sub  = lane & 3;       // channel quad index (lo half)
    int node = warp * 8 + oct;
    bool alive = node < n;

    const ulonglong2* u2l = (const ulonglong2*)u;  // 16B = 2x f32x2
    float bv = b[lane];        // hoisted off the epilogue's dependent chain

    int cnt = 0;
    ulonglong2 alo = make_ulonglong2(0ULL, 0ULL);
    ulonglong2 ahi = make_ulonglong2(0ULL, 0ULL);
    if (alive) {
        int rs = g_rowstart[node];
        cnt = g_cnt[node];
        int pc = (cnt + 3) & ~3;
        ulonglong2 slo = u2l[node * 8 + sub];
        ulonglong2 shi = u2l[node * 8 + 4 + sub];
        unsigned long long cc = bcast2((float)(1 - (pc - cnt)));
        alo.x = mulx2(slo.x, cc); alo.y = mulx2(slo.y, cc);
        ahi.x = mulx2(shi.x, cc); ahi.y = mulx2(shi.y, cc);
        for (int j = rs; j < rs + pc; j += 4) {
            int4 e = *(const int4*)(g_adjs + j);
            ulonglong2 v0 = u2l[e.x * 8 + sub];
            ulonglong2 w0 = u2l[e.x * 8 + 4 + sub];
            ulonglong2 v1 = u2l[e.y * 8 + sub];
            ulonglong2 w1 = u2l[e.y * 8 + 4 + sub];
            ulonglong2 v2 = u2l[e.z * 8 + sub];
            ulonglong2 w2 = u2l[e.z * 8 + 4 + sub];
            ulonglong2 v3 = u2l[e.w * 8 + sub];
            ulonglong2 w3 = u2l[e.w * 8 + 4 + sub];
            addx2(alo.x, v0.x); addx2(alo.y, v0.y);
            addx2(ahi.x, w0.x); addx2(ahi.y, w0.y);
            addx2(alo.x, v1.x); addx2(alo.y, v1.y);
            addx2(ahi.x, w1.x); addx2(ahi.y, w1.y);
            addx2(alo.x, v2.x); addx2(alo.y, v2.y);
            addx2(ahi.x, w2.x); addx2(ahi.y, w2.y);
            addx2(alo.x, v3.x); addx2(alo.y, v3.y);
            addx2(ahi.x, w3.x); addx2(ahi.y, w3.y);
        }
    }

    // stage all 8 nodes' t rows (bytes of f32x2 pairs == 4 floats in order)
    int wslot = (tid >> 5) * 256;
    *(ulonglong2*)(sT + wslot + oct * 32 + 4 * sub) = alo;
    *(ulonglong2*)(sT + wslot + oct * 32 + 16 + 4 * sub) = ahi;
    __syncwarp();

    // eight full-warp GEMVs, one per node
    int warp8 = warp * 8;
    const float* wr = sWt + lane * 36;
#pragma unroll
    for (int h = 0; h < 8; h++) {
        int nd = warp8 + h;
        if (nd >= n) break;
        int cn = __shfl_sync(0xFFFFFFFFu, cnt, h << 2);
        float dis = rsqrtf((float)(cn + 1));
        const float4* t4p = (const float4*)(sT + wslot + h * 32);
        float s = 0.0f;
#pragma unroll
        for (int p = 0; p < 8; p++) {
            float4 t4 = t4p[p];
            float4 w4 = *(const float4*)(wr + 4 * p);
            s += t4.x * w4.x + t4.y * w4.y;
            s += t4.z * w4.z + t4.w * w4.w;
        }
        float o = dis * bv + (dis * dis) * s;   // pre-scaled output
        if (RELU_OUT) o = fmaxf(o, 0.0f);       // producer-side relu (exact)
        out[nd * 32 + lane] = o;
    }
}

// Fused dual head: one aggregation per node (pure adds; u already relu'd),
// two smem GEMVs (mu and logvar), unscaled raw outputs.
__global__ __launch_bounds__(256) void k_layer2(
    const float* __restrict__ u,
    const float* __restrict__ Wa, const float* __restrict__ Wb,
    const float* __restrict__ ba, const float* __restrict__ bb,
    float* __restrict__ oa, float* __restrict__ ob, int n)
{
    __shared__ float4 sWtav[288];
    __shared__ float4 sWtbv[288];
    __shared__ float4 sTv[512];
    float* sWta = (float*)sWtav;
    float* sWtb = (float*)sWtbv;
    float* sT   = (float*)sTv;
    int tid = threadIdx.x;
#pragma unroll
    for (int it = 0; it < 4; it++) {
        int idx = tid + it * 256;
        float wa = Wa[idx];
        float wb = Wb[idx];
        int k = idx >> 5, j = idx & 31;
        sWta[j * 36 + k] = wa;
        sWtb[j * 36 + k] = wb;
    }
    __syncthreads();

    int warp = (blockIdx.x * blockDim.x + tid) >> 5;
    int lane = tid & 31;
    int oct  = lane >> 2;
    int sub  = lane & 3;
    int node = warp * 8 + oct;
    bool alive = node < n;

    const ulonglong2* u2l = (const ulonglong2*)u;
    float bav = ba[lane];   // hoisted
    float bbv = bb[lane];   // hoisted

    int cnt = 0;
    ulonglong2 alo = make_ulonglong2(0ULL, 0ULL);
    ulonglong2 ahi = make_ulonglong2(0ULL, 0ULL);
    if (alive) {
        int rs = g_rowstart[node];
        cnt = g_cnt[node];
        int pc = (cnt + 3) & ~3;
        ulonglong2 slo = u2l[node * 8 + sub];
        ulonglong2 shi = u2l[node * 8 + 4 + sub];
        unsigned long long cc = bcast2((float)(1 - (pc - cnt)));
        alo.x = mulx2(slo.x, cc); alo.y = mulx2(slo.y, cc);
        ahi.x = mulx2(shi.x, cc); ahi.y = mulx2(shi.y, cc);
        for (int j = rs; j < rs + pc; j += 4) {
            int4 e = *(const int4*)(g_adjs + j);
            ulonglong2 v0 = u2l[e.x * 8 + sub];
            ulonglong2 w0 = u2l[e.x * 8 + 4 + sub];
            ulonglong2 v1 = u2l[e.y * 8 + sub];
            ulonglong2 w1 = u2l[e.y * 8 + 4 + sub];
            ulonglong2 v2 = u2l[e.z * 8 + sub];
            ulonglong2 w2 = u2l[e.z * 8 + 4 + sub];
            ulonglong2 v3 = u2l[e.w * 8 + sub];
            ulonglong2 w3 = u2l[e.w * 8 + 4 + sub];
            addx2(alo.x, v0.x); addx2(alo.y, v0.y);
            addx2(ahi.x, w0.x); addx2(ahi.y, w0.y);
            addx2(alo.x, v1.x); addx2(alo.y, v1.y);
            addx2(ahi.x, w1.x); addx2(ahi.y, w1.y);
            addx2(alo.x, v2.x); addx2(alo.y, v2.y);
            addx2(ahi.x, w2.x); addx2(ahi.y, w2.y);
            addx2(alo.x, v3.x); addx2(alo.y, v3.y);
            addx2(ahi.x, w3.x); addx2(ahi.y, w3.y);
        }
    }

    int wslot = (tid >> 5) * 256;
    *(ulonglong2*)(sT + wslot + oct * 32 + 4 * sub) = alo;
    *(ulonglong2*)(sT + wslot + oct * 32 + 16 + 4 * sub) = ahi;
    __syncwarp();

    int warp8 = warp * 8;
    const float* wra = sWta + lane * 36;
    const float* wrb = sWtb + lane * 36;
#pragma unroll
    for (int h = 0; h < 8; h++) {
        int nd = warp8 + h;
        if (nd >= n) break;
        int cn = __shfl_sync(0xFFFFFFFFu, cnt, h << 2);
        float dis = rsqrtf((float)(cn + 1));
        const float4* t4p = (const float4*)(sT + wslot + h * 32);
        float sa = 0.0f, sb = 0.0f;
#pragma unroll
        for (int p = 0; p < 8; p++) {
            float4 t4 = t4p[p];
            float4 wa = *(const float4*)(wra + 4 * p);
            float4 wb = *(const float4*)(wrb + 4 * p);
            sa += t4.x * wa.x + t4.y * wa.y;
            sa += t4.z * wa.z + t4.w * wa.w;
            sb += t4.x * wb.x + t4.y * wb.y;
            sb += t4.z * wb.z + t4.w * wb.w;
        }
        oa[nd * 32 + lane] = bav + dis * sa;
        ob[nd * 32 + lane] = bbv + dis * sb;
    }
}

// ---------------------------------------------------------------------------
// Launch
// ---------------------------------------------------------------------------

static inline int cdiv(long long a, int b) { return (int)((a + b - 1) / b); }

extern "C" void kernel_launch(void* const* d_in, const int* in_sizes, int n_in,
                              void* d_out, int out_size)
{
    const float* x   = (const float*)d_in[0];
    const void*  ei  = d_in[1];
    const float* W1  = (const float*)d_in[2];
    const float* b1  = (const float*)d_in[3];
    const float* W2  = (const float*)d_in[4];
    const float* b2  = (const float*)d_in[5];
    const float* Wmu = (const float*)d_in[6];
    const float* bmu = (const float*)d_in[7];
    const float* Wlv = (const float*)d_in[8];
    const float* blv = (const float*)d_in[9];

    int N = in_sizes[0] / 32;
    int E = in_sizes[1] / 2;

    float* mu = (float*)d_out;
    float* lv = mu + (size_t)N * 32;

    float* bufA; float* bufB;
    cudaGetSymbolAddress((void**)&bufA, g_bufA);
    cudaGetSymbolAddress((void**)&bufB, g_bufB);

    const int T = 256;
    int gN  = cdiv(N, T);                  // per-node
    int gE  = cdiv(E, T);                  // per-edge
    int gE4 = cdiv(E, T * 4);              // 4 edges per thread
    int gP  = cdiv((long long)N * 8, T);   // per-float4 (rowalloc+prescale grid)
    int gO  = cdiv((long long)N * 4, T);   // eighth-warp-per-node (layers)

    // CSR build (src-only payload, x4 self-padded rows); rowalloc fused with
    // layer-1 pre-scale on the dense grid (preserves warp-aggregated atomic).
    k_init<<<gN, T>>>((const int*)ei, E, N);
    k_count<<<gE4, T>>>(ei, E);
    k_rowalloc<<<gP, T>>>(x, bufA, N);
    k_permute<<<gE, T>>>(ei, E);

    // Layer 1: u2 = relu(dis (.) ((A u1) @ W1 + b1))   [relu stored]
    k_layer<1><<<gO, T>>>(bufA, W1, b1, bufB, N);
    // Layer 2: u3 = relu(dis (.) ((A u2) @ W2 + b2))   [relu stored]
    k_layer<1><<<gO, T>>>(bufB, W2, b2, bufA, N);
    // Heads: t = A u3; mu = dis*(t@Wmu) + bmu; lv = dis*(t@Wlv) + blv
    k_layer2<<<gO, T>>>(bufA, Wmu, Wlv, bmu, blv, mu, lv, N);
}